// round 12
// baseline (speedup 1.0000x reference)
#include <cuda_runtime.h>
#include <cstdint>

// Problem dims (fixed by the dataset)
#define B_DIM 128
#define T_DIM 128
#define I_DIM 1024
#define O_DIM 1024
#define BT_DIM 16384          // B*T
#define BTO_SZ 16777216       // B*T*O
#define IO_SZ  1048576        // I*O

// ---------------- static device scratch (no allocations allowed) ----------------
__device__ float g_h[BTO_SZ];                       // h = x @ w    [B*T, O] fp32
__device__ float g_d[O_DIM * O_DIM];                // d = w^T w    [O, O]
__device__ float g_spk[BTO_SZ];                     // spike scratch (fallback)
__device__ float g_invn[O_DIM];                     // 1/(norm+eps)
__device__ int   g_cnt;

__global__ void zero_cnt_kernel() { g_cnt = 0; }

__device__ __forceinline__ uint32_t smem_u32(const void* p) {
    uint32_t a;
    asm("{ .reg .u64 t; cvta.to.shared.u64 t, %1; cvt.u32.u64 %0, t; }" : "=r"(a) : "l"(p));
    return a;
}
#define CP_ASYNC16(dst, src) \
    asm volatile("cp.async.cg.shared.global [%0], [%1], 16;" :: "r"(dst), "l"(src))
#define CP_COMMIT() asm volatile("cp.async.commit_group;")
#define CP_WAIT0()  asm volatile("cp.async.wait_group 0;" ::: "memory")

// ==================== h = x @ w : fp32 packed-pair FMA, k-order-preserving ====================
// BITWISE CONTRACT: each output is a single fp32 accumulator updated by IEEE fp32
// FMA with k ascending 0..1023 — identical chains to R7..R10 (rel_err 0.0).
// 512 threads/CTA, thread tile 4x8: ~75 regs/thread -> 16 warps/SM with NO reg cap
// (R10's (256,2) cap spilled; R9 ncu showed issue=44%/fma=63% at 8 warps).
__global__ void __launch_bounds__(512)
h_sgemm_kernel(const float* __restrict__ A,   // x [16384, 1024] row-major
               const float* __restrict__ B,   // w [1024, 1024]  row-major (k-major)
               float* __restrict__ C)
{
    __shared__ __align__(16) float As[2][8][132];   // [stage][k][m]
    __shared__ __align__(16) float Bs[2][8][128];   // [stage][k][n]

    const int tid  = threadIdx.x;
    const int bx   = blockIdx.x;            // N tile (8)
    const int by   = blockIdx.y;            // M tile (128)
    const int trow = tid >> 4;              // 0..31 (4 rows each)
    const int tcol = tid & 15;              // 0..15 (8 cols each: tcol*4 and 64+tcol*4)

    const bool is_a = (tid < 256);
    // A load slot (threads 0..255): one float4 (row = tid/2, k-half = (tid&1)*4)
    const int a_row = tid >> 1;
    const int a_k   = (tid & 1) * 4;
    const float* a_src = is_a ? (A + (size_t)(by * 128 + a_row) * I_DIM + a_k) : nullptr;

    // B cp.async slot (threads 256..511): one 16B chunk
    const int bidx  = tid - 256;
    const int b_k   = bidx >> 5;
    const int b_col = (bidx & 31) * 4;
    const float* b_src = B + (size_t)b_k * O_DIM + bx * 128 + b_col;
    const uint32_t bs_dst[2] = { smem_u32(&Bs[0][b_k][b_col]), smem_u32(&Bs[1][b_k][b_col]) };

    // acc2[i][j2]: packed pair (col 2*j2, 2*j2+1) of fp32 accumulators, 4 rows
    unsigned long long acc2[4][4];
#pragma unroll
    for (int i = 0; i < 4; ++i)
#pragma unroll
        for (int j = 0; j < 4; ++j) acc2[i][j] = 0ULL;

    // ---- prolog: stage 0 ----
    float4 areg = make_float4(0.f, 0.f, 0.f, 0.f);
    if (is_a) areg = *(const float4*)a_src;
    else      CP_ASYNC16(bs_dst[0], b_src);
    CP_COMMIT();
    if (is_a) {
        As[0][a_k + 0][a_row] = areg.x;
        As[0][a_k + 1][a_row] = areg.y;
        As[0][a_k + 2][a_row] = areg.z;
        As[0][a_k + 3][a_row] = areg.w;
    }
    CP_WAIT0();
    __syncthreads();

    for (int k0 = 0; k0 < I_DIM; k0 += 8) {
        const int  buf      = (k0 >> 3) & 1;
        const bool has_next = (k0 + 8) < I_DIM;
        if (has_next) {
            if (is_a) areg = *(const float4*)(a_src + k0 + 8);
            else      CP_ASYNC16(bs_dst[buf ^ 1], b_src + (size_t)(k0 + 8) * O_DIM);
        }
        CP_COMMIT();

#pragma unroll
        for (int kk = 0; kk < 8; ++kk) {
            float a[4];
            *(float4*)a = *(const float4*)&As[buf][kk][trow * 4];
            const ulonglong2 b01 = *(const ulonglong2*)&Bs[buf][kk][tcol * 4];
            const ulonglong2 b23 = *(const ulonglong2*)&Bs[buf][kk][64 + tcol * 4];
            const unsigned long long b2[4] = { b01.x, b01.y, b23.x, b23.y };
#pragma unroll
            for (int i = 0; i < 4; ++i) {
                unsigned long long a2;
                asm("mov.b64 %0, {%1, %1};" : "=l"(a2) : "f"(a[i]));
#pragma unroll
                for (int j = 0; j < 4; ++j)
                    asm("fma.rn.f32x2 %0, %1, %2, %0;"
                        : "+l"(acc2[i][j]) : "l"(a2), "l"(b2[j]));
            }
        }

        if (has_next && is_a) {
            const int nb = buf ^ 1;
            As[nb][a_k + 0][a_row] = areg.x;
            As[nb][a_k + 1][a_row] = areg.y;
            As[nb][a_k + 2][a_row] = areg.z;
            As[nb][a_k + 3][a_row] = areg.w;
        }
        CP_WAIT0();
        __syncthreads();
    }

    // ---- epilogue: 4 rows, cols {tcol*4..+3} ∪ {64+tcol*4..+3} ----
#pragma unroll
    for (int i = 0; i < 4; ++i) {
        const int m = by * 128 + trow * 4 + i;
        float* crow = C + (size_t)m * O_DIM + bx * 128;
        *(ulonglong2*)&crow[tcol * 4]      = make_ulonglong2(acc2[i][0], acc2[i][1]);
        *(ulonglong2*)&crow[64 + tcol * 4] = make_ulonglong2(acc2[i][2], acc2[i][3]);
    }
}

// ---------------- fp32 tiled GEMM (A^T @ B), used for d = w^T w (unchanged — passed) ----------------
__global__ void sgemm_at_kernel(const float* __restrict__ A,
                                const float* __restrict__ Bm,
                                float* __restrict__ C,
                                int M, int N, int K)
{
    __shared__ float As[8][128];
    __shared__ float Bs[8][128];
    const int tid = threadIdx.x;
    const int bx = blockIdx.x, by = blockIdx.y;
    const int trow = tid / 16, tcol = tid % 16;

    float acc[8][8];
#pragma unroll
    for (int i = 0; i < 8; ++i)
#pragma unroll
        for (int j = 0; j < 8; ++j) acc[i][j] = 0.f;

    for (int k0 = 0; k0 < K; k0 += 8) {
        {
            const int kk = tid >> 5, c4 = (tid & 31) * 4;
            const float4 av = *(const float4*)&A[(size_t)(k0 + kk) * M + by * 128 + c4];
            As[kk][c4 + 0] = av.x; As[kk][c4 + 1] = av.y; As[kk][c4 + 2] = av.z; As[kk][c4 + 3] = av.w;
            const float4 bv = *(const float4*)&Bm[(size_t)(k0 + kk) * N + bx * 128 + c4];
            Bs[kk][c4 + 0] = bv.x; Bs[kk][c4 + 1] = bv.y; Bs[kk][c4 + 2] = bv.z; Bs[kk][c4 + 3] = bv.w;
        }
        __syncthreads();
#pragma unroll
        for (int kk = 0; kk < 8; ++kk) {
            float4 a0 = *(const float4*)&As[kk][trow * 8 + 0];
            float4 a1 = *(const float4*)&As[kk][trow * 8 + 4];
            float4 b0 = *(const float4*)&Bs[kk][tcol * 8 + 0];
            float4 b1 = *(const float4*)&Bs[kk][tcol * 8 + 4];
            float a[8] = {a0.x, a0.y, a0.z, a0.w, a1.x, a1.y, a1.z, a1.w};
            float b[8] = {b0.x, b0.y, b0.z, b0.w, b1.x, b1.y, b1.z, b1.w};
#pragma unroll
            for (int i = 0; i < 8; ++i)
#pragma unroll
                for (int j = 0; j < 8; ++j)
                    acc[i][j] = fmaf(a[i], b[j], acc[i][j]);
        }
        __syncthreads();
    }
#pragma unroll
    for (int i = 0; i < 8; ++i) {
        const size_t r = (size_t)(by * 128 + trow * 8 + i) * N + bx * 128 + tcol * 8;
#pragma unroll
        for (int j = 0; j < 8; j += 4)
            *(float4*)&C[r + j] = make_float4(acc[i][j], acc[i][j + 1], acc[i][j + 2], acc[i][j + 3]);
    }
}

__global__ void invnorm_kernel()
{
    const int o = threadIdx.x;
    g_invn[o] = 1.0f / (g_d[(size_t)o * O_DIM + o] + 1e-8f);
}

// ---------------- fused recurrent scan: 2 barriers/step, MLP-8 rst, h prefetch ----------------
// Spike list index-sorted (ascending o); rst adds run strictly ascending -> bitwise-identical.
__global__ void __launch_bounds__(1024, 1)
scan_kernel(const float* __restrict__ beta_p,
            const float* __restrict__ b_p,
            float* __restrict__ spk_out)
{
    const int b = blockIdx.x, o = threadIdx.x;
    const int wid = o >> 5, lane = o & 31;

    __shared__ int list[O_DIM];
    __shared__ int warp_cnt[32];

    const float beta = beta_p[0];
    const float ombt = 1.0f - beta;
    const float invn = g_invn[o];
    const float bo   = b_p[o];
    float mem = 0.0f;
    int   n = 0;
    int   tot_spikes = 0;

    const float* __restrict__ hb = g_h + (size_t)b * T_DIM * O_DIM + o;
    float* __restrict__ sb = spk_out + (size_t)b * T_DIM * O_DIM + o;

    float hcur = hb[0];   // prefetch t=0

    for (int t = 0; t < T_DIM; ++t) {
        // prefetch next step's h before the latency-heavy rst gather
        float hnext = 0.0f;
        if (t + 1 < T_DIM) hnext = hb[(size_t)(t + 1) * O_DIM];

        // rst: 8-wide load batches (MLP), adds in ascending-k order
        float rst = 0.0f;
        int k = 0;
        for (; k + 8 <= n; k += 8) {
            const int j0 = list[k + 0], j1 = list[k + 1], j2 = list[k + 2], j3 = list[k + 3];
            const int j4 = list[k + 4], j5 = list[k + 5], j6 = list[k + 6], j7 = list[k + 7];
            const float v0 = __ldg(&g_d[(size_t)j0 * O_DIM + o]);
            const float v1 = __ldg(&g_d[(size_t)j1 * O_DIM + o]);
            const float v2 = __ldg(&g_d[(size_t)j2 * O_DIM + o]);
            const float v3 = __ldg(&g_d[(size_t)j3 * O_DIM + o]);
            const float v4 = __ldg(&g_d[(size_t)j4 * O_DIM + o]);
            const float v5 = __ldg(&g_d[(size_t)j5 * O_DIM + o]);
            const float v6 = __ldg(&g_d[(size_t)j6 * O_DIM + o]);
            const float v7 = __ldg(&g_d[(size_t)j7 * O_DIM + o]);
            rst += v0; rst += v1; rst += v2; rst += v3;
            rst += v4; rst += v5; rst += v6; rst += v7;
        }
        for (; k < n; ++k)
            rst += __ldg(&g_d[(size_t)list[k] * O_DIM + o]);

        mem = (mem - rst) * beta + hcur * ombt;
        hcur = hnext;
        const float mthr = mem * invn - bo;
        const float s = (mthr > 0.0f) ? 1.0f : 0.0f;
        sb[(size_t)t * O_DIM] = s;

        const unsigned m = __ballot_sync(0xffffffffu, s > 0.0f);
        if (lane == 0) warp_cnt[wid] = __popc(m);
        __syncthreads();   // counts visible; separates list reads from writes

        int x = warp_cnt[lane];
#pragma unroll
        for (int dlt = 1; dlt < 32; dlt <<= 1) {
            int y = __shfl_up_sync(0xffffffffu, x, dlt);
            if (lane >= dlt) x += y;
        }
        const int total = __shfl_sync(0xffffffffu, x, 31);
        const int off   = (wid == 0) ? 0 : __shfl_sync(0xffffffffu, x, wid - 1);

        if (s > 0.0f)
            list[off + __popc(m & ((1u << lane) - 1u))] = o;
        n = total;
        if (o == 0) tot_spikes += total;
        __syncthreads();   // list ready for next step
    }

    if (o == 0) atomicAdd(&g_cnt, tot_spikes);
}

__global__ void finalize_kernel(float* out, int loss_idx)
{
    out[loss_idx] = 0.5f * (float)g_cnt / (float)BTO_SZ;
}

// ==================== host side ====================
extern "C" void kernel_launch(void* const* d_in, const int* in_sizes, int n_in,
                              void* d_out, int out_size)
{
    const float *x = nullptr, *w = nullptr, *beta = nullptr, *bvec = nullptr;
    for (int i = 0; i < n_in; ++i) {
        switch (in_sizes[i]) {
            case BTO_SZ:  x    = (const float*)d_in[i]; break;
            case IO_SZ:   w    = (const float*)d_in[i]; break;
            case 1:       beta = (const float*)d_in[i]; break;
            case O_DIM:   bvec = (const float*)d_in[i]; break;
            default: break;
        }
    }

    float* out = (float*)d_out;
    float* spk_dst;
    bool   write_loss;
    int    loss_idx = 0;
    if (out_size >= BTO_SZ + 1) {
        spk_dst = out; write_loss = true; loss_idx = BTO_SZ;
    } else if (out_size == BTO_SZ) {
        spk_dst = out; write_loss = false;
    } else {
        void* p = nullptr; cudaGetSymbolAddress(&p, g_spk);
        spk_dst = (float*)p; write_loss = true; loss_idx = (out_size > 0) ? out_size - 1 : 0;
    }

    float* h_ptr; { void* p; cudaGetSymbolAddress(&p, g_h); h_ptr = (float*)p; }
    float* d_ptr; { void* p; cudaGetSymbolAddress(&p, g_d); d_ptr = (float*)p; }

    zero_cnt_kernel<<<1, 1>>>();

    // h = x @ w : k-order-preserving fp32 via packed fma.rn.f32x2, 512 thr, 16 warps/SM
    {
        dim3 grid(O_DIM / 128, BT_DIM / 128);   // (8, 128)
        h_sgemm_kernel<<<grid, 512>>>(x, w, h_ptr);
    }

    // d = w^T w in strict fp32 (unchanged)
    {
        dim3 grid(O_DIM / 128, O_DIM / 128);
        sgemm_at_kernel<<<grid, 256>>>(w, w, d_ptr, O_DIM, O_DIM, I_DIM);
    }
    invnorm_kernel<<<1, O_DIM>>>();

    scan_kernel<<<B_DIM, 1024>>>(beta, bvec, spk_dst);

    if (write_loss) finalize_kernel<<<1, 1>>>(out, loss_idx);
}

// round 13
// speedup vs baseline: 1.3357x; 1.3357x over previous
#include <cuda_runtime.h>
#include <cstdint>

// Problem dims (fixed by the dataset)
#define B_DIM 128
#define T_DIM 128
#define I_DIM 1024
#define O_DIM 1024
#define BT_DIM 16384          // B*T
#define BTO_SZ 16777216       // B*T*O
#define IO_SZ  1048576        // I*O

// ---------------- static device scratch (no allocations allowed) ----------------
__device__ float g_h[BTO_SZ];                       // h = x @ w    [B*T, O] fp32
__device__ float g_d[O_DIM * O_DIM];                // d = w^T w    [O, O]
__device__ float g_spk[BTO_SZ];                     // spike scratch (fallback)
__device__ float g_invn[O_DIM];                     // 1/(norm+eps)
__device__ int   g_cnt;

__global__ void zero_cnt_kernel() { g_cnt = 0; }

__device__ __forceinline__ uint32_t smem_u32(const void* p) {
    uint32_t a;
    asm("{ .reg .u64 t; cvta.to.shared.u64 t, %1; cvt.u32.u64 %0, t; }" : "=r"(a) : "l"(p));
    return a;
}
#define CP_ASYNC16(dst, src) \
    asm volatile("cp.async.cg.shared.global [%0], [%1], 16;" :: "r"(dst), "l"(src))
#define CP_COMMIT() asm volatile("cp.async.commit_group;")
#define CP_WAIT0()  asm volatile("cp.async.wait_group 0;" ::: "memory")

// ==================== h = x @ w : EXACT R8 kernel (907.7us run) ====================
// BITWISE CONTRACT: each output = single fp32 accumulator, IEEE FMA, k ascending.
// At the FFMA2 rt-3 banked ceiling (~680us) — do not touch occupancy or tiling.
__global__ void __launch_bounds__(256)
h_sgemm_kernel(const float* __restrict__ A,   // x [16384, 1024] row-major
               const float* __restrict__ B,   // w [1024, 1024]  row-major (k-major)
               float* __restrict__ C)
{
    __shared__ __align__(16) float As[2][8][132];   // [stage][k][m]
    __shared__ __align__(16) float Bs[2][8][128];   // [stage][k][n]

    const int tid  = threadIdx.x;
    const int bx   = blockIdx.x;            // N tile (8)
    const int by   = blockIdx.y;            // M tile (128)
    const int trow = tid >> 4;              // 0..15
    const int tcol = tid & 15;              // 0..15

    const int a_row = tid >> 1;
    const int a_k   = (tid & 1) * 4;
    const float* a_src = A + (size_t)(by * 128 + a_row) * I_DIM + a_k;

    const int b_k   = tid >> 5;
    const int b_col = (tid & 31) * 4;
    const float* b_src = B + (size_t)b_k * O_DIM + bx * 128 + b_col;
    const uint32_t bs_dst[2] = { smem_u32(&Bs[0][b_k][b_col]), smem_u32(&Bs[1][b_k][b_col]) };

    unsigned long long acc2[8][4];
#pragma unroll
    for (int i = 0; i < 8; ++i)
#pragma unroll
        for (int j = 0; j < 4; ++j) acc2[i][j] = 0ULL;

    float4 areg = *(const float4*)a_src;
    CP_ASYNC16(bs_dst[0], b_src);
    CP_COMMIT();
    As[0][a_k + 0][a_row] = areg.x;
    As[0][a_k + 1][a_row] = areg.y;
    As[0][a_k + 2][a_row] = areg.z;
    As[0][a_k + 3][a_row] = areg.w;
    CP_WAIT0();
    __syncthreads();

    for (int k0 = 0; k0 < I_DIM; k0 += 8) {
        const int  buf      = (k0 >> 3) & 1;
        const bool has_next = (k0 + 8) < I_DIM;
        if (has_next) {
            areg = *(const float4*)(a_src + k0 + 8);
            CP_ASYNC16(bs_dst[buf ^ 1], b_src + (size_t)(k0 + 8) * O_DIM);
        }
        CP_COMMIT();

#pragma unroll
        for (int kk = 0; kk < 8; ++kk) {
            float a[8];
            *(float4*)&a[0] = *(const float4*)&As[buf][kk][trow * 4];
            *(float4*)&a[4] = *(const float4*)&As[buf][kk][64 + trow * 4];
            const ulonglong2 b01 = *(const ulonglong2*)&Bs[buf][kk][tcol * 4];
            const ulonglong2 b23 = *(const ulonglong2*)&Bs[buf][kk][64 + tcol * 4];
            const unsigned long long b2[4] = { b01.x, b01.y, b23.x, b23.y };
#pragma unroll
            for (int i = 0; i < 8; ++i) {
                unsigned long long a2;
                asm("mov.b64 %0, {%1, %1};" : "=l"(a2) : "f"(a[i]));
#pragma unroll
                for (int j = 0; j < 4; ++j)
                    asm("fma.rn.f32x2 %0, %1, %2, %0;"
                        : "+l"(acc2[i][j]) : "l"(a2), "l"(b2[j]));
            }
        }

        if (has_next) {
            const int nb = buf ^ 1;
            As[nb][a_k + 0][a_row] = areg.x;
            As[nb][a_k + 1][a_row] = areg.y;
            As[nb][a_k + 2][a_row] = areg.z;
            As[nb][a_k + 3][a_row] = areg.w;
        }
        CP_WAIT0();
        __syncthreads();
    }

#pragma unroll
    for (int ih = 0; ih < 2; ++ih)
#pragma unroll
        for (int i = 0; i < 4; ++i) {
            const int m = by * 128 + ih * 64 + trow * 4 + i;
            float* crow = C + (size_t)m * O_DIM + bx * 128;
            const int ai = ih * 4 + i;
            *(ulonglong2*)&crow[tcol * 4]      = make_ulonglong2(acc2[ai][0], acc2[ai][1]);
            *(ulonglong2*)&crow[64 + tcol * 4] = make_ulonglong2(acc2[ai][2], acc2[ai][3]);
        }
}

// ---------------- fp32 tiled GEMM (A^T @ B), used for d = w^T w (unchanged — passed) ----------------
__global__ void sgemm_at_kernel(const float* __restrict__ A,
                                const float* __restrict__ Bm,
                                float* __restrict__ C,
                                int M, int N, int K)
{
    __shared__ float As[8][128];
    __shared__ float Bs[8][128];
    const int tid = threadIdx.x;
    const int bx = blockIdx.x, by = blockIdx.y;
    const int trow = tid / 16, tcol = tid % 16;

    float acc[8][8];
#pragma unroll
    for (int i = 0; i < 8; ++i)
#pragma unroll
        for (int j = 0; j < 8; ++j) acc[i][j] = 0.f;

    for (int k0 = 0; k0 < K; k0 += 8) {
        {
            const int kk = tid >> 5, c4 = (tid & 31) * 4;
            const float4 av = *(const float4*)&A[(size_t)(k0 + kk) * M + by * 128 + c4];
            As[kk][c4 + 0] = av.x; As[kk][c4 + 1] = av.y; As[kk][c4 + 2] = av.z; As[kk][c4 + 3] = av.w;
            const float4 bv = *(const float4*)&Bm[(size_t)(k0 + kk) * N + bx * 128 + c4];
            Bs[kk][c4 + 0] = bv.x; Bs[kk][c4 + 1] = bv.y; Bs[kk][c4 + 2] = bv.z; Bs[kk][c4 + 3] = bv.w;
        }
        __syncthreads();
#pragma unroll
        for (int kk = 0; kk < 8; ++kk) {
            float4 a0 = *(const float4*)&As[kk][trow * 8 + 0];
            float4 a1 = *(const float4*)&As[kk][trow * 8 + 4];
            float4 b0 = *(const float4*)&Bs[kk][tcol * 8 + 0];
            float4 b1 = *(const float4*)&Bs[kk][tcol * 8 + 4];
            float a[8] = {a0.x, a0.y, a0.z, a0.w, a1.x, a1.y, a1.z, a1.w};
            float b[8] = {b0.x, b0.y, b0.z, b0.w, b1.x, b1.y, b1.z, b1.w};
#pragma unroll
            for (int i = 0; i < 8; ++i)
#pragma unroll
                for (int j = 0; j < 8; ++j)
                    acc[i][j] = fmaf(a[i], b[j], acc[i][j]);
        }
        __syncthreads();
    }
#pragma unroll
    for (int i = 0; i < 8; ++i) {
        const size_t r = (size_t)(by * 128 + trow * 8 + i) * N + bx * 128 + tcol * 8;
#pragma unroll
        for (int j = 0; j < 8; j += 4)
            *(float4*)&C[r + j] = make_float4(acc[i][j], acc[i][j + 1], acc[i][j + 2], acc[i][j + 3]);
    }
}

__global__ void invnorm_kernel()
{
    const int o = threadIdx.x;
    g_invn[o] = 1.0f / (g_d[(size_t)o * O_DIM + o] + 1e-8f);
}

// ---------------- fused recurrent scan: 2 barriers/step, MLP-8 rst, h prefetch ----------------
// Spike list index-sorted (ascending o); rst adds run strictly ascending -> bitwise-identical.
__global__ void __launch_bounds__(1024, 1)
scan_kernel(const float* __restrict__ beta_p,
            const float* __restrict__ b_p,
            float* __restrict__ spk_out)
{
    const int b = blockIdx.x, o = threadIdx.x;
    const int wid = o >> 5, lane = o & 31;

    __shared__ int list[O_DIM];
    __shared__ int warp_cnt[32];

    const float beta = beta_p[0];
    const float ombt = 1.0f - beta;
    const float invn = g_invn[o];
    const float bo   = b_p[o];
    float mem = 0.0f;
    int   n = 0;
    int   tot_spikes = 0;

    const float* __restrict__ hb = g_h + (size_t)b * T_DIM * O_DIM + o;
    float* __restrict__ sb = spk_out + (size_t)b * T_DIM * O_DIM + o;

    float hcur = hb[0];   // prefetch t=0

    for (int t = 0; t < T_DIM; ++t) {
        float hnext = 0.0f;
        if (t + 1 < T_DIM) hnext = hb[(size_t)(t + 1) * O_DIM];

        // rst: 8-wide load batches (MLP), adds in ascending-k order
        float rst = 0.0f;
        int k = 0;
        for (; k + 8 <= n; k += 8) {
            const int j0 = list[k + 0], j1 = list[k + 1], j2 = list[k + 2], j3 = list[k + 3];
            const int j4 = list[k + 4], j5 = list[k + 5], j6 = list[k + 6], j7 = list[k + 7];
            const float v0 = __ldg(&g_d[(size_t)j0 * O_DIM + o]);
            const float v1 = __ldg(&g_d[(size_t)j1 * O_DIM + o]);
            const float v2 = __ldg(&g_d[(size_t)j2 * O_DIM + o]);
            const float v3 = __ldg(&g_d[(size_t)j3 * O_DIM + o]);
            const float v4 = __ldg(&g_d[(size_t)j4 * O_DIM + o]);
            const float v5 = __ldg(&g_d[(size_t)j5 * O_DIM + o]);
            const float v6 = __ldg(&g_d[(size_t)j6 * O_DIM + o]);
            const float v7 = __ldg(&g_d[(size_t)j7 * O_DIM + o]);
            rst += v0; rst += v1; rst += v2; rst += v3;
            rst += v4; rst += v5; rst += v6; rst += v7;
        }
        for (; k < n; ++k)
            rst += __ldg(&g_d[(size_t)list[k] * O_DIM + o]);

        mem = (mem - rst) * beta + hcur * ombt;
        hcur = hnext;
        const float mthr = mem * invn - bo;
        const float s = (mthr > 0.0f) ? 1.0f : 0.0f;
        sb[(size_t)t * O_DIM] = s;

        const unsigned m = __ballot_sync(0xffffffffu, s > 0.0f);
        if (lane == 0) warp_cnt[wid] = __popc(m);
        __syncthreads();   // counts visible; separates list reads from writes

        int x = warp_cnt[lane];
#pragma unroll
        for (int dlt = 1; dlt < 32; dlt <<= 1) {
            int y = __shfl_up_sync(0xffffffffu, x, dlt);
            if (lane >= dlt) x += y;
        }
        const int total = __shfl_sync(0xffffffffu, x, 31);
        const int off   = (wid == 0) ? 0 : __shfl_sync(0xffffffffu, x, wid - 1);

        if (s > 0.0f)
            list[off + __popc(m & ((1u << lane) - 1u))] = o;
        n = total;
        if (o == 0) tot_spikes += total;
        __syncthreads();   // list ready for next step
    }

    if (o == 0) atomicAdd(&g_cnt, tot_spikes);
}

__global__ void finalize_kernel(float* out, int loss_idx)
{
    out[loss_idx] = 0.5f * (float)g_cnt / (float)BTO_SZ;
}

// ==================== host side ====================
extern "C" void kernel_launch(void* const* d_in, const int* in_sizes, int n_in,
                              void* d_out, int out_size)
{
    const float *x = nullptr, *w = nullptr, *beta = nullptr, *bvec = nullptr;
    for (int i = 0; i < n_in; ++i) {
        switch (in_sizes[i]) {
            case BTO_SZ:  x    = (const float*)d_in[i]; break;
            case IO_SZ:   w    = (const float*)d_in[i]; break;
            case 1:       beta = (const float*)d_in[i]; break;
            case O_DIM:   bvec = (const float*)d_in[i]; break;
            default: break;
        }
    }

    float* out = (float*)d_out;
    float* spk_dst;
    bool   write_loss;
    int    loss_idx = 0;
    if (out_size >= BTO_SZ + 1) {
        spk_dst = out; write_loss = true; loss_idx = BTO_SZ;
    } else if (out_size == BTO_SZ) {
        spk_dst = out; write_loss = false;
    } else {
        void* p = nullptr; cudaGetSymbolAddress(&p, g_spk);
        spk_dst = (float*)p; write_loss = true; loss_idx = (out_size > 0) ? out_size - 1 : 0;
    }

    float* h_ptr; { void* p; cudaGetSymbolAddress(&p, g_h); h_ptr = (float*)p; }
    float* d_ptr; { void* p; cudaGetSymbolAddress(&p, g_d); d_ptr = (float*)p; }

    zero_cnt_kernel<<<1, 1>>>();

    // h = x @ w : EXACT R8 winner (FFMA2 ceiling)
    {
        dim3 grid(O_DIM / 128, BT_DIM / 128);   // (8, 128)
        h_sgemm_kernel<<<grid, 256>>>(x, w, h_ptr);
    }

    // d = w^T w in strict fp32 (serial)
    {
        dim3 grid(O_DIM / 128, O_DIM / 128);
        sgemm_at_kernel<<<grid, 256>>>(w, w, d_ptr, O_DIM, O_DIM, I_DIM);
    }
    invnorm_kernel<<<1, O_DIM>>>();

    scan_kernel<<<B_DIM, 1024>>>(beta, bvec, spk_dst);

    if (write_loss) finalize_kernel<<<1, 1>>>(out, loss_idx);
}

// round 15
// speedup vs baseline: 1.4040x; 1.0511x over previous
#include <cuda_runtime.h>
#include <cstdint>

// Problem dims (fixed by the dataset)
#define B_DIM 128
#define T_DIM 128
#define I_DIM 1024
#define O_DIM 1024
#define BT_DIM 16384          // B*T
#define BTO_SZ 16777216       // B*T*O
#define IO_SZ  1048576        // I*O

// ---------------- static device scratch (no allocations allowed) ----------------
__device__ float g_h[BTO_SZ];                       // h = x @ w    [B*T, O] fp32
__device__ float g_d[O_DIM * O_DIM];                // d = w^T w    [O, O]
__device__ float g_spk[BTO_SZ];                     // spike scratch (fallback)
__device__ float g_invn[O_DIM];                     // 1/(norm+eps)
__device__ int   g_cnt;

__device__ __forceinline__ uint32_t smem_u32(const void* p) {
    uint32_t a;
    asm("{ .reg .u64 t; cvta.to.shared.u64 t, %1; cvt.u32.u64 %0, t; }" : "=r"(a) : "l"(p));
    return a;
}
#define CP_ASYNC16(dst, src) \
    asm volatile("cp.async.cg.shared.global [%0], [%1], 16;" :: "r"(dst), "l"(src))
#define CP_COMMIT() asm volatile("cp.async.commit_group;")
#define CP_WAIT0()  asm volatile("cp.async.wait_group 0;" ::: "memory")

// ==================== h = x @ w : EXACT R8/R13 kernel ====================
// BITWISE CONTRACT: each output = single fp32 accumulator, IEEE FMA, k ascending.
// At the FFMA2 rt-3 banked ceiling (~680us) — do not touch occupancy or tiling.
__global__ void __launch_bounds__(256)
h_sgemm_kernel(const float* __restrict__ A,   // x [16384, 1024] row-major
               const float* __restrict__ B,   // w [1024, 1024]  row-major (k-major)
               float* __restrict__ C)
{
    __shared__ __align__(16) float As[2][8][132];   // [stage][k][m]
    __shared__ __align__(16) float Bs[2][8][128];   // [stage][k][n]

    const int tid  = threadIdx.x;
    const int bx   = blockIdx.x;            // N tile (8)
    const int by   = blockIdx.y;            // M tile (128)
    const int trow = tid >> 4;              // 0..15
    const int tcol = tid & 15;              // 0..15

    const int a_row = tid >> 1;
    const int a_k   = (tid & 1) * 4;
    const float* a_src = A + (size_t)(by * 128 + a_row) * I_DIM + a_k;

    const int b_k   = tid >> 5;
    const int b_col = (tid & 31) * 4;
    const float* b_src = B + (size_t)b_k * O_DIM + bx * 128 + b_col;
    const uint32_t bs_dst[2] = { smem_u32(&Bs[0][b_k][b_col]), smem_u32(&Bs[1][b_k][b_col]) };

    unsigned long long acc2[8][4];
#pragma unroll
    for (int i = 0; i < 8; ++i)
#pragma unroll
        for (int j = 0; j < 4; ++j) acc2[i][j] = 0ULL;

    float4 areg = *(const float4*)a_src;
    CP_ASYNC16(bs_dst[0], b_src);
    CP_COMMIT();
    As[0][a_k + 0][a_row] = areg.x;
    As[0][a_k + 1][a_row] = areg.y;
    As[0][a_k + 2][a_row] = areg.z;
    As[0][a_k + 3][a_row] = areg.w;
    CP_WAIT0();
    __syncthreads();

    for (int k0 = 0; k0 < I_DIM; k0 += 8) {
        const int  buf      = (k0 >> 3) & 1;
        const bool has_next = (k0 + 8) < I_DIM;
        if (has_next) {
            areg = *(const float4*)(a_src + k0 + 8);
            CP_ASYNC16(bs_dst[buf ^ 1], b_src + (size_t)(k0 + 8) * O_DIM);
        }
        CP_COMMIT();

#pragma unroll
        for (int kk = 0; kk < 8; ++kk) {
            float a[8];
            *(float4*)&a[0] = *(const float4*)&As[buf][kk][trow * 4];
            *(float4*)&a[4] = *(const float4*)&As[buf][kk][64 + trow * 4];
            const ulonglong2 b01 = *(const ulonglong2*)&Bs[buf][kk][tcol * 4];
            const ulonglong2 b23 = *(const ulonglong2*)&Bs[buf][kk][64 + tcol * 4];
            const unsigned long long b2[4] = { b01.x, b01.y, b23.x, b23.y };
#pragma unroll
            for (int i = 0; i < 8; ++i) {
                unsigned long long a2;
                asm("mov.b64 %0, {%1, %1};" : "=l"(a2) : "f"(a[i]));
#pragma unroll
                for (int j = 0; j < 4; ++j)
                    asm("fma.rn.f32x2 %0, %1, %2, %0;"
                        : "+l"(acc2[i][j]) : "l"(a2), "l"(b2[j]));
            }
        }

        if (has_next) {
            const int nb = buf ^ 1;
            As[nb][a_k + 0][a_row] = areg.x;
            As[nb][a_k + 1][a_row] = areg.y;
            As[nb][a_k + 2][a_row] = areg.z;
            As[nb][a_k + 3][a_row] = areg.w;
        }
        CP_WAIT0();
        __syncthreads();
    }

#pragma unroll
    for (int ih = 0; ih < 2; ++ih)
#pragma unroll
        for (int i = 0; i < 4; ++i) {
            const int m = by * 128 + ih * 64 + trow * 4 + i;
            float* crow = C + (size_t)m * O_DIM + bx * 128;
            const int ai = ih * 4 + i;
            *(ulonglong2*)&crow[tcol * 4]      = make_ulonglong2(acc2[ai][0], acc2[ai][1]);
            *(ulonglong2*)&crow[64 + tcol * 4] = make_ulonglong2(acc2[ai][2], acc2[ai][3]);
        }
}

// ---------------- fp32 tiled GEMM (A^T @ B), used for d = w^T w (unchanged — passed) ----------------
__global__ void sgemm_at_kernel(const float* __restrict__ A,
                                const float* __restrict__ Bm,
                                float* __restrict__ C,
                                int M, int N, int K)
{
    __shared__ float As[8][128];
    __shared__ float Bs[8][128];
    const int tid = threadIdx.x;
    const int bx = blockIdx.x, by = blockIdx.y;
    const int trow = tid / 16, tcol = tid % 16;

    float acc[8][8];
#pragma unroll
    for (int i = 0; i < 8; ++i)
#pragma unroll
        for (int j = 0; j < 8; ++j) acc[i][j] = 0.f;

    for (int k0 = 0; k0 < K; k0 += 8) {
        {
            const int kk = tid >> 5, c4 = (tid & 31) * 4;
            const float4 av = *(const float4*)&A[(size_t)(k0 + kk) * M + by * 128 + c4];
            As[kk][c4 + 0] = av.x; As[kk][c4 + 1] = av.y; As[kk][c4 + 2] = av.z; As[kk][c4 + 3] = av.w;
            const float4 bv = *(const float4*)&Bm[(size_t)(k0 + kk) * N + bx * 128 + c4];
            Bs[kk][c4 + 0] = bv.x; Bs[kk][c4 + 1] = bv.y; Bs[kk][c4 + 2] = bv.z; Bs[kk][c4 + 3] = bv.w;
        }
        __syncthreads();
#pragma unroll
        for (int kk = 0; kk < 8; ++kk) {
            float4 a0 = *(const float4*)&As[kk][trow * 8 + 0];
            float4 a1 = *(const float4*)&As[kk][trow * 8 + 4];
            float4 b0 = *(const float4*)&Bs[kk][tcol * 8 + 0];
            float4 b1 = *(const float4*)&Bs[kk][tcol * 8 + 4];
            float a[8] = {a0.x, a0.y, a0.z, a0.w, a1.x, a1.y, a1.z, a1.w};
            float b[8] = {b0.x, b0.y, b0.z, b0.w, b1.x, b1.y, b1.z, b1.w};
#pragma unroll
            for (int i = 0; i < 8; ++i)
#pragma unroll
                for (int j = 0; j < 8; ++j)
                    acc[i][j] = fmaf(a[i], b[j], acc[i][j]);
        }
        __syncthreads();
    }
#pragma unroll
    for (int i = 0; i < 8; ++i) {
        const size_t r = (size_t)(by * 128 + trow * 8 + i) * N + bx * 128 + tcol * 8;
#pragma unroll
        for (int j = 0; j < 8; j += 4)
            *(float4*)&C[r + j] = make_float4(acc[i][j], acc[i][j + 1], acc[i][j + 2], acc[i][j + 3]);
    }
}

// invnorm + counter reset folded into one launch
__global__ void invnorm_kernel()
{
    const int o = threadIdx.x;
    if (o == 0) g_cnt = 0;
    g_invn[o] = 1.0f / (g_d[(size_t)o * O_DIM + o] + 1e-8f);
}

// ---------------- fused recurrent scan: 2 barriers/step, MLP-8 rst, h prefetch ----------------
// Spike list index-sorted (ascending o); rst adds run strictly ascending -> bitwise-identical.
__global__ void __launch_bounds__(1024, 1)
scan_kernel(const float* __restrict__ beta_p,
            const float* __restrict__ b_p,
            float* __restrict__ spk_out)
{
    const int b = blockIdx.x, o = threadIdx.x;
    const int wid = o >> 5, lane = o & 31;

    __shared__ int list[O_DIM];
    __shared__ int warp_cnt[32];

    const float beta = beta_p[0];
    const float ombt = 1.0f - beta;
    const float invn = g_invn[o];
    const float bo   = b_p[o];
    float mem = 0.0f;
    int   n = 0;
    int   tot_spikes = 0;

    const float* __restrict__ hb = g_h + (size_t)b * T_DIM * O_DIM + o;
    float* __restrict__ sb = spk_out + (size_t)b * T_DIM * O_DIM + o;

    float hcur = hb[0];   // prefetch t=0

    for (int t = 0; t < T_DIM; ++t) {
        float hnext = 0.0f;
        if (t + 1 < T_DIM) hnext = hb[(size_t)(t + 1) * O_DIM];

        // rst: 8-wide load batches (MLP), adds in ascending-k order
        float rst = 0.0f;
        int k = 0;
        for (; k + 8 <= n; k += 8) {
            const int j0 = list[k + 0], j1 = list[k + 1], j2 = list[k + 2], j3 = list[k + 3];
            const int j4 = list[k + 4], j5 = list[k + 5], j6 = list[k + 6], j7 = list[k + 7];
            const float v0 = __ldg(&g_d[(size_t)j0 * O_DIM + o]);
            const float v1 = __ldg(&g_d[(size_t)j1 * O_DIM + o]);
            const float v2 = __ldg(&g_d[(size_t)j2 * O_DIM + o]);
            const float v3 = __ldg(&g_d[(size_t)j3 * O_DIM + o]);
            const float v4 = __ldg(&g_d[(size_t)j4 * O_DIM + o]);
            const float v5 = __ldg(&g_d[(size_t)j5 * O_DIM + o]);
            const float v6 = __ldg(&g_d[(size_t)j6 * O_DIM + o]);
            const float v7 = __ldg(&g_d[(size_t)j7 * O_DIM + o]);
            rst += v0; rst += v1; rst += v2; rst += v3;
            rst += v4; rst += v5; rst += v6; rst += v7;
        }
        for (; k < n; ++k)
            rst += __ldg(&g_d[(size_t)list[k] * O_DIM + o]);

        mem = (mem - rst) * beta + hcur * ombt;
        hcur = hnext;
        const float mthr = mem * invn - bo;
        const float s = (mthr > 0.0f) ? 1.0f : 0.0f;
        sb[(size_t)t * O_DIM] = s;

        const unsigned m = __ballot_sync(0xffffffffu, s > 0.0f);
        if (lane == 0) warp_cnt[wid] = __popc(m);
        __syncthreads();   // counts visible; separates list reads from writes

        int x = warp_cnt[lane];
#pragma unroll
        for (int dlt = 1; dlt < 32; dlt <<= 1) {
            int y = __shfl_up_sync(0xffffffffu, x, dlt);
            if (lane >= dlt) x += y;
        }
        const int total = __shfl_sync(0xffffffffu, x, 31);
        const int off   = (wid == 0) ? 0 : __shfl_sync(0xffffffffu, x, wid - 1);

        if (s > 0.0f)
            list[off + __popc(m & ((1u << lane) - 1u))] = o;
        n = total;
        if (o == 0) tot_spikes += total;
        __syncthreads();   // list ready for next step
    }

    if (o == 0) atomicAdd(&g_cnt, tot_spikes);
}

__global__ void finalize_kernel(float* out, int loss_idx)
{
    out[loss_idx] = 0.5f * (float)g_cnt / (float)BTO_SZ;
}

// ==================== host side ====================
extern "C" void kernel_launch(void* const* d_in, const int* in_sizes, int n_in,
                              void* d_out, int out_size)
{
    const float *x = nullptr, *w = nullptr, *beta = nullptr, *bvec = nullptr;
    for (int i = 0; i < n_in; ++i) {
        switch (in_sizes[i]) {
            case BTO_SZ:  x    = (const float*)d_in[i]; break;
            case IO_SZ:   w    = (const float*)d_in[i]; break;
            case 1:       beta = (const float*)d_in[i]; break;
            case O_DIM:   bvec = (const float*)d_in[i]; break;
            default: break;
        }
    }

    float* out = (float*)d_out;
    float* spk_dst;
    bool   write_loss;
    int    loss_idx = 0;
    if (out_size >= BTO_SZ + 1) {
        spk_dst = out; write_loss = true; loss_idx = BTO_SZ;
    } else if (out_size == BTO_SZ) {
        spk_dst = out; write_loss = false;
    } else {
        void* p = nullptr; cudaGetSymbolAddress(&p, g_spk);
        spk_dst = (float*)p; write_loss = true; loss_idx = (out_size > 0) ? out_size - 1 : 0;
    }

    float* h_ptr; { void* p; cudaGetSymbolAddress(&p, g_h); h_ptr = (float*)p; }
    float* d_ptr; { void* p; cudaGetSymbolAddress(&p, g_d); d_ptr = (float*)p; }

    // one-time side-stream resources (created on the first, non-captured call)
    static cudaStream_t s2 = nullptr;
    static cudaEvent_t  evA = nullptr, evB = nullptr;
    if (!s2) {
        cudaStreamCreateWithFlags(&s2, cudaStreamNonBlocking);
        cudaEventCreateWithFlags(&evA, cudaEventDisableTiming);
        cudaEventCreateWithFlags(&evB, cudaEventDisableTiming);
    }

    // fork: d = w^T w (+ invnorm/counter reset) on side stream, concurrent with h
    cudaEventRecord(evA, 0);
    cudaStreamWaitEvent(s2, evA, 0);
    {
        dim3 grid(O_DIM / 128, O_DIM / 128);    // 64 CTAs — fills h's tail waves
        sgemm_at_kernel<<<grid, 256, 0, s2>>>(w, w, d_ptr, O_DIM, O_DIM, I_DIM);
    }
    invnorm_kernel<<<1, O_DIM, 0, s2>>>();
    cudaEventRecord(evB, s2);

    // h = x @ w : EXACT R8/R13 winner (FFMA2 ceiling), main stream
    {
        dim3 grid(O_DIM / 128, BT_DIM / 128);   // (8, 128)
        h_sgemm_kernel<<<grid, 256>>>(x, w, h_ptr);
    }

    // join: scan needs both h and d/invnorm
    cudaStreamWaitEvent(0, evB, 0);
    scan_kernel<<<B_DIM, 1024>>>(beta, bvec, spk_dst);

    if (write_loss) finalize_kernel<<<1, 1>>>(out, loss_idx);
}